// round 12
// baseline (speedup 1.0000x reference)
#include <cuda_runtime.h>
#include <cuda_bf16.h>
#include <math.h>
#include <stdint.h>

// Problem: B=4, T=2048, D=2048, HEADS=16
// Chain (all fused around one templated mma.sync GEMM engine):
//   K1a: k0 = x @ w_qk[0:2048]^T  [1 prod]  epilogue -> kth (bf16 hi, transposed)
//   K1b: v  = x @ w_qk[2048:]^T   [3 prod]  epilogue -> vh (hi) + vth/vtl (transposed split)
//   K2:  s = scale * kth @ vh^T   [1 prod]  fp32
//   K3:  softmax rows -> ah/al splits
//   K4:  q = a @ vt^T             [3 prod]  epilogue -> qgh/qgl (gathered head-permuted split)
//   K5:  out = qg @ w_dense^T + b [3 prod]
// Engine: m16n8k16 bf16, XOR-swizzled 64B smem rows, cp.async ring
// (RING=6 for 1-product, RING=3 for 3-product), single sync/chunk, 2 CTAs/SM.

// ---------------------------------------------------------------- scratch ---
static __device__ float g_s [16777216];   // 4*2048*2048

static __device__ __nv_bfloat16 g_xh[16777216],  g_xl[16777216];
static __device__ __nv_bfloat16 g_wqh[8388608],  g_wql[8388608];
static __device__ __nv_bfloat16 g_wdh[4194304],  g_wdl[4194304];
static __device__ __nv_bfloat16 g_kth[16777216];                   // k0^T hi
static __device__ __nv_bfloat16 g_vh [16777216];                   // v hi
static __device__ __nv_bfloat16 g_vth[16777216], g_vtl[16777216];  // v^T split
static __device__ __nv_bfloat16 g_ah [16777216], g_al [16777216];
static __device__ __nv_bfloat16 g_qgh[16777216], g_qgl[16777216];

// --------------------------------------------------------------- helpers ---
__device__ __forceinline__ uint32_t smem_u32(const void* p) {
    uint32_t a;
    asm("{ .reg .u64 t; cvta.to.shared.u64 t, %1; cvt.u32.u64 %0, t; }"
        : "=r"(a) : "l"(p));
    return a;
}
__device__ __forceinline__ void cp16(uint32_t dst, const void* src) {
    asm volatile("cp.async.cg.shared.global [%0], [%1], 16;"
                 :: "r"(dst), "l"(src) : "memory");
}
#define CP_COMMIT() asm volatile("cp.async.commit_group;" ::: "memory")

__device__ __forceinline__ void ldsm4(uint32_t* r, uint32_t addr) {
    asm volatile("ldmatrix.sync.aligned.m8n8.x4.shared.b16 {%0,%1,%2,%3}, [%4];"
                 : "=r"(r[0]), "=r"(r[1]), "=r"(r[2]), "=r"(r[3]) : "r"(addr));
}
__device__ __forceinline__ void mma16816(float* c, const uint32_t* a, const uint32_t* b) {
    asm volatile(
        "mma.sync.aligned.m16n8k16.row.col.f32.bf16.bf16.f32 "
        "{%0,%1,%2,%3}, {%4,%5,%6,%7}, {%8,%9}, {%0,%1,%2,%3};"
        : "+f"(c[0]), "+f"(c[1]), "+f"(c[2]), "+f"(c[3])
        : "r"(a[0]), "r"(a[1]), "r"(a[2]), "r"(a[3]), "r"(b[0]), "r"(b[1]));
}

__device__ __forceinline__ void split1(float x, __nv_bfloat16& h, __nv_bfloat16& l) {
    h = __float2bfloat16(x);
    l = __float2bfloat16(x - __bfloat162float(h));
}

// ------------------------------------------------------------ bf16 GEMM ----
// C(m,n) = alpha*sum_k A(m,k)*B(n,k) [+bias(n)]
// NPROD: 3 = hh+hl+lh, 1 = hh only (half loads, 6-deep ring).
// EPI: 0 fp32 C (+bias)
//      1 gather-split: row r=(m&127)*64 + z*16 + (m>>7) -> gh/gl bf16 splits
//      2 transpose hi: gh[b][n][m] = bf16(acc)           (b = m0>>11)
//      3 direct hi to g2[b][m][n] + transpose split to gh/gl[b][n][m]
#define GK       2048
#define GBK      32
#define NCHUNK   (GK / GBK)        // 64
#define ROWB     64u
#define TILE_B   (128u * ROWB)     // 8192
#define GEMM_SMEM 98304u           // 3x32KB or 6x16KB; also >= 68KB epi buffer
#define SSQ      4194304ull        // 2048*2048
#define EPIP     133               // fp32 staging pitch

__device__ __forceinline__ uint32_t swz(uint32_t row, uint32_t c) {
    return row * ROWB + ((c ^ ((row >> 1) & 3u)) << 4);
}

template<int NPROD, int EPI>
__global__ __launch_bounds__(256, 2)
void gemm_mma(const __nv_bfloat16* __restrict__ Ah, const __nv_bfloat16* __restrict__ Al,
              size_t strideA,
              const __nv_bfloat16* __restrict__ Bh, const __nv_bfloat16* __restrict__ Bl,
              size_t strideB,
              float* __restrict__ C, int ldc, size_t strideC,
              float alpha, const float* __restrict__ bias,
              __nv_bfloat16* __restrict__ gh, __nv_bfloat16* __restrict__ gl,
              __nv_bfloat16* __restrict__ g2)
{
    extern __shared__ char smem[];
    const uint32_t sbase = smem_u32(smem);

    constexpr int RING = (NPROD == 1) ? 6 : 3;
    constexpr uint32_t STAGE = (NPROD == 1) ? (2u * TILE_B) : (4u * TILE_B);
    constexpr uint32_t O_AH = 0u;
    constexpr uint32_t O_BH = (NPROD == 1) ? TILE_B : 2u * TILE_B;
    constexpr uint32_t O_AL = TILE_B;
    constexpr uint32_t O_BL = 3u * TILE_B;

    const int tid  = threadIdx.x;
    const int lane = tid & 31;
    const int wid  = tid >> 5;
    const int wm0  = (wid & 1) * 64;
    const int wn0  = (wid >> 1) * 32;

    Ah += blockIdx.z * strideA;
    Bh += blockIdx.z * strideB;
    if (NPROD == 3) { Al += blockIdx.z * strideA; Bl += blockIdx.z * strideB; }
    if (EPI == 0) C += blockIdx.z * strideC;
    const int m0 = blockIdx.y * 128;
    const int n0 = blockIdx.x * 128;

    const int lc = tid & 3;
    const int lr = tid >> 2;

    auto load_stage = [&](int t) {
        if (t < NCHUNK) {
            const uint32_t sb = sbase + (uint32_t)(t % RING) * STAGE;
            const int ks = t * GBK;
#pragma unroll
            for (int i = 0; i < 2; i++) {
                const uint32_t row = (uint32_t)(lr + i * 64);
                const uint32_t d = swz(row, (uint32_t)lc);
                const size_t aoff = (size_t)(m0 + row) * GK + ks + lc * 8;
                const size_t boff = (size_t)(n0 + row) * GK + ks + lc * 8;
                cp16(sb + O_AH + d, Ah + aoff);
                cp16(sb + O_BH + d, Bh + boff);
                if (NPROD == 3) {
                    cp16(sb + O_AL + d, Al + aoff);
                    cp16(sb + O_BL + d, Bl + boff);
                }
            }
        }
        CP_COMMIT();
    };

    float acc[4][4][4];
#pragma unroll
    for (int i = 0; i < 4; i++)
#pragma unroll
        for (int j = 0; j < 4; j++)
#pragma unroll
            for (int k = 0; k < 4; k++) acc[i][j][k] = 0.f;

    const uint32_t a_row = (uint32_t)(wm0 + (lane & 15));
    const uint32_t a_s   = (a_row >> 1) & 3u;
    const uint32_t a_hi  = (uint32_t)(lane >> 4);
    const uint32_t a_base = a_row * ROWB;
    const uint32_t a_x0 = ((a_hi ^ a_s) << 4);
    const uint32_t a_x1 = (((2u | a_hi) ^ a_s) << 4);

    const uint32_t b_row = (uint32_t)(wn0 + ((lane >> 4) & 1) * 8 + (lane & 7));
    const uint32_t b_s   = (b_row >> 1) & 3u;
    const uint32_t b_hi  = (uint32_t)((lane >> 3) & 1);
    const uint32_t b_base = b_row * ROWB;
    const uint32_t b_x0 = ((b_hi ^ b_s) << 4);
    const uint32_t b_x1 = (((2u | b_hi) ^ b_s) << 4);

#pragma unroll
    for (int i = 0; i < RING - 1; i++) load_stage(i);

    for (int t = 0; t < NCHUNK; t++) {
        asm volatile("cp.async.wait_group %0;" :: "n"(RING - 2));
        __syncthreads();
        load_stage(t + RING - 1);

        const uint32_t sb = sbase + (uint32_t)(t % RING) * STAGE;
#pragma unroll
        for (int k16 = 0; k16 < 2; k16++) {
            const uint32_t ax = k16 ? a_x1 : a_x0;
            const uint32_t bx = k16 ? b_x1 : b_x0;
            uint32_t ah[4][4], bh[2][4];
#pragma unroll
            for (int mt = 0; mt < 4; mt++)
                ldsm4(ah[mt], sb + O_AH + a_base + (uint32_t)mt * (16u * ROWB) + ax);
#pragma unroll
            for (int p = 0; p < 2; p++)
                ldsm4(bh[p], sb + O_BH + b_base + (uint32_t)p * (16u * ROWB) + bx);
#pragma unroll
            for (int mt = 0; mt < 4; mt++)
#pragma unroll
                for (int p = 0; p < 2; p++) {
                    mma16816(acc[mt][2 * p + 0], ah[mt], &bh[p][0]);
                    mma16816(acc[mt][2 * p + 1], ah[mt], &bh[p][2]);
                }
            if (NPROD == 3) {
                {
                    uint32_t bl[2][4];
#pragma unroll
                    for (int p = 0; p < 2; p++)
                        ldsm4(bl[p], sb + O_BL + b_base + (uint32_t)p * (16u * ROWB) + bx);
#pragma unroll
                    for (int mt = 0; mt < 4; mt++)
#pragma unroll
                        for (int p = 0; p < 2; p++) {
                            mma16816(acc[mt][2 * p + 0], ah[mt], &bl[p][0]);
                            mma16816(acc[mt][2 * p + 1], ah[mt], &bl[p][2]);
                        }
                }
                {
                    uint32_t al[4][4];
#pragma unroll
                    for (int mt = 0; mt < 4; mt++)
                        ldsm4(al[mt], sb + O_AL + a_base + (uint32_t)mt * (16u * ROWB) + ax);
#pragma unroll
                    for (int mt = 0; mt < 4; mt++)
#pragma unroll
                        for (int p = 0; p < 2; p++) {
                            mma16816(acc[mt][2 * p + 0], al[mt], &bh[p][0]);
                            mma16816(acc[mt][2 * p + 1], al[mt], &bh[p][2]);
                        }
                }
            }
        }
    }

    // ---- epilogues ----
    const int er = lane >> 2;
    const int ec = (lane & 3) * 2;

    if (EPI == 0) {
#pragma unroll
        for (int mt = 0; mt < 4; mt++)
#pragma unroll
            for (int nt = 0; nt < 4; nt++) {
                int m = m0 + wm0 + mt * 16 + er;
                int n = n0 + wn0 + nt * 8 + ec;
                float b0 = 0.f, b1 = 0.f;
                if (bias) { b0 = __ldg(bias + n); b1 = __ldg(bias + n + 1); }
                float2 v0, v1;
                v0.x = alpha * acc[mt][nt][0] + b0;
                v0.y = alpha * acc[mt][nt][1] + b1;
                v1.x = alpha * acc[mt][nt][2] + b0;
                v1.y = alpha * acc[mt][nt][3] + b1;
                *(float2*)&C[(size_t)m * (size_t)ldc + n]       = v0;
                *(float2*)&C[(size_t)(m + 8) * (size_t)ldc + n] = v1;
            }
    }
    if (EPI == 1) {
        const int b = (int)blockIdx.z;
#pragma unroll
        for (int mt = 0; mt < 4; mt++)
#pragma unroll
            for (int nt = 0; nt < 4; nt++) {
                int m = m0 + wm0 + mt * 16 + er;
                int n = n0 + wn0 + nt * 8 + ec;
                int r1 = ((m & 127) << 6) + b * 16 + (m >> 7);
                int m2 = m + 8;
                int r2 = ((m2 & 127) << 6) + b * 16 + (m2 >> 7);
                __nv_bfloat16 h0, l0, h1, l1;
                split1(acc[mt][nt][0], h0, l0);
                split1(acc[mt][nt][1], h1, l1);
                *(__nv_bfloat162*)(gh + (size_t)r1 * 2048 + n) = __halves2bfloat162(h0, h1);
                *(__nv_bfloat162*)(gl + (size_t)r1 * 2048 + n) = __halves2bfloat162(l0, l1);
                split1(acc[mt][nt][2], h0, l0);
                split1(acc[mt][nt][3], h1, l1);
                *(__nv_bfloat162*)(gh + (size_t)r2 * 2048 + n) = __halves2bfloat162(h0, h1);
                *(__nv_bfloat162*)(gl + (size_t)r2 * 2048 + n) = __halves2bfloat162(l0, l1);
            }
    }
    if (EPI == 2 || EPI == 3) {
        const int b  = m0 >> 11;
        const int t0 = m0 & 2047;
        if (EPI == 3) {
            // direct hi write: g2[b][m][n] = bf16(acc)
#pragma unroll
            for (int mt = 0; mt < 4; mt++)
#pragma unroll
                for (int nt = 0; nt < 4; nt++) {
                    int m = m0 + wm0 + mt * 16 + er;
                    int n = n0 + wn0 + nt * 8 + ec;
                    int t1 = m & 2047, t2 = (m + 8) & 2047;
                    *(__nv_bfloat162*)(g2 + (size_t)b * SSQ + (size_t)t1 * 2048 + n) =
                        __halves2bfloat162(__float2bfloat16(acc[mt][nt][0]),
                                           __float2bfloat16(acc[mt][nt][1]));
                    *(__nv_bfloat162*)(g2 + (size_t)b * SSQ + (size_t)t2 * 2048 + n) =
                        __halves2bfloat162(__float2bfloat16(acc[mt][nt][2]),
                                           __float2bfloat16(acc[mt][nt][3]));
                }
        }
        // stage fp32 transposed tile in smem, then write gh (+gl)
        __syncthreads();                 // mainloop smem reads done everywhere
        float* st = (float*)smem;
#pragma unroll
        for (int mt = 0; mt < 4; mt++)
#pragma unroll
            for (int nt = 0; nt < 4; nt++) {
                int m = wm0 + mt * 16 + er;
                int n = wn0 + nt * 8 + ec;
                st[(size_t)n * EPIP + m]           = acc[mt][nt][0];
                st[(size_t)(n + 1) * EPIP + m]     = acc[mt][nt][1];
                st[(size_t)n * EPIP + m + 8]       = acc[mt][nt][2];
                st[(size_t)(n + 1) * EPIP + m + 8] = acc[mt][nt][3];
            }
        __syncthreads();
        const int r  = tid & 127;        // local transposed row (= n index)
        const int ch = tid >> 7;         // col half
        const float* src = st + (size_t)r * EPIP + ch * 64;
        size_t dbase = (size_t)b * SSQ + (size_t)(n0 + r) * 2048 + t0 + ch * 64;
#pragma unroll
        for (int j = 0; j < 64; j += 2) {
            float x0 = src[j], x1 = src[j + 1];
            if (EPI == 2) {
                *(__nv_bfloat162*)(gh + dbase + j) =
                    __halves2bfloat162(__float2bfloat16(x0), __float2bfloat16(x1));
            } else {
                __nv_bfloat16 h0, l0, h1, l1;
                split1(x0, h0, l0); split1(x1, h1, l1);
                *(__nv_bfloat162*)(gh + dbase + j) = __halves2bfloat162(h0, h1);
                *(__nv_bfloat162*)(gl + dbase + j) = __halves2bfloat162(l0, l1);
            }
        }
    }
}

// ----------------------------------------------------------- prep kernels ---
__global__ __launch_bounds__(256)
void copy_split_k(const float* __restrict__ src, size_t src_rstride, size_t src_bstride,
                  __nv_bfloat16* __restrict__ dh, __nv_bfloat16* __restrict__ dl,
                  size_t dst_bstride)
{
    size_t row = blockIdx.y;
    size_t col = (size_t)blockIdx.x * 1024 + threadIdx.x * 4;
    float4 v = *(const float4*)(src + (size_t)blockIdx.z * src_bstride + row * src_rstride + col);
    __nv_bfloat16 h0, h1, h2, h3, l0, l1, l2, l3;
    split1(v.x, h0, l0); split1(v.y, h1, l1);
    split1(v.z, h2, l2); split1(v.w, h3, l3);
    size_t o = (size_t)blockIdx.z * dst_bstride + row * 2048 + col;
    ((__nv_bfloat162*)(dh + o))[0] = __halves2bfloat162(h0, h1);
    ((__nv_bfloat162*)(dh + o))[1] = __halves2bfloat162(h2, h3);
    if (dl) {
        ((__nv_bfloat162*)(dl + o))[0] = __halves2bfloat162(l0, l1);
        ((__nv_bfloat162*)(dl + o))[1] = __halves2bfloat162(l2, l3);
    }
}

__global__ __launch_bounds__(256)
void softmax_split_k(const float* __restrict__ s,
                     __nv_bfloat16* __restrict__ ah, __nv_bfloat16* __restrict__ al)
{
    const float* p = s + (size_t)blockIdx.x * 2048;
    int tid = threadIdx.x, warp = tid >> 5, lane = tid & 31;
    __shared__ float red[8];

    float4 v0 = *(const float4*)(p + tid * 4);
    float4 v1 = *(const float4*)(p + 1024 + tid * 4);

    float m = fmaxf(fmaxf(fmaxf(v0.x, v0.y), fmaxf(v0.z, v0.w)),
                    fmaxf(fmaxf(v1.x, v1.y), fmaxf(v1.z, v1.w)));
#pragma unroll
    for (int o = 16; o > 0; o >>= 1) m = fmaxf(m, __shfl_xor_sync(0xffffffffu, m, o));
    if (lane == 0) red[warp] = m;
    __syncthreads();
    float bm = red[0];
#pragma unroll
    for (int i = 1; i < 8; i++) bm = fmaxf(bm, red[i]);
    __syncthreads();

    v0.x = __expf(v0.x - bm); v0.y = __expf(v0.y - bm);
    v0.z = __expf(v0.z - bm); v0.w = __expf(v0.w - bm);
    v1.x = __expf(v1.x - bm); v1.y = __expf(v1.y - bm);
    v1.z = __expf(v1.z - bm); v1.w = __expf(v1.w - bm);

    float sm = v0.x + v0.y + v0.z + v0.w + v1.x + v1.y + v1.z + v1.w;
#pragma unroll
    for (int o = 16; o > 0; o >>= 1) sm += __shfl_xor_sync(0xffffffffu, sm, o);
    if (lane == 0) red[warp] = sm;
    __syncthreads();
    float tot = red[0];
#pragma unroll
    for (int i = 1; i < 8; i++) tot += red[i];
    float inv = 1.f / tot;

    size_t base = (size_t)blockIdx.x * 2048;
    float vals[8] = {v0.x * inv, v0.y * inv, v0.z * inv, v0.w * inv,
                     v1.x * inv, v1.y * inv, v1.z * inv, v1.w * inv};
    size_t offs[2] = {base + tid * 4, base + 1024 + tid * 4};
#pragma unroll
    for (int half = 0; half < 2; half++) {
        __nv_bfloat16 h0, h1, h2, h3, l0, l1, l2, l3;
        split1(vals[half * 4 + 0], h0, l0); split1(vals[half * 4 + 1], h1, l1);
        split1(vals[half * 4 + 2], h2, l2); split1(vals[half * 4 + 3], h3, l3);
        size_t o = offs[half];
        ((__nv_bfloat162*)(ah + o))[0] = __halves2bfloat162(h0, h1);
        ((__nv_bfloat162*)(ah + o))[1] = __halves2bfloat162(h2, h3);
        ((__nv_bfloat162*)(al + o))[0] = __halves2bfloat162(l0, l1);
        ((__nv_bfloat162*)(al + o))[1] = __halves2bfloat162(l2, l3);
    }
}

// ------------------------------------------------------------------ driver ---
extern "C" void kernel_launch(void* const* d_in, const int* in_sizes, int n_in,
                              void* d_out, int out_size)
{
    const float* x       = (const float*)d_in[0];
    const float* w_qk    = (const float*)d_in[1];
    const float* w_dense = (const float*)d_in[2];
    const float* b_dense = (const float*)d_in[3];
    float* out = (float*)d_out;

    float *s;
    cudaGetSymbolAddress((void**)&s, g_s);
    __nv_bfloat16 *xh, *xl, *wqh, *wql, *wdh, *wdl, *kth, *vh,
                  *vth, *vtl, *ah, *al, *qgh, *qgl;
    cudaGetSymbolAddress((void**)&xh,  g_xh);  cudaGetSymbolAddress((void**)&xl,  g_xl);
    cudaGetSymbolAddress((void**)&wqh, g_wqh); cudaGetSymbolAddress((void**)&wql, g_wql);
    cudaGetSymbolAddress((void**)&wdh, g_wdh); cudaGetSymbolAddress((void**)&wdl, g_wdl);
    cudaGetSymbolAddress((void**)&kth, g_kth);
    cudaGetSymbolAddress((void**)&vh,  g_vh);
    cudaGetSymbolAddress((void**)&vth, g_vth); cudaGetSymbolAddress((void**)&vtl, g_vtl);
    cudaGetSymbolAddress((void**)&ah,  g_ah);  cudaGetSymbolAddress((void**)&al,  g_al);
    cudaGetSymbolAddress((void**)&qgh, g_qgh); cudaGetSymbolAddress((void**)&qgl, g_qgl);

    cudaFuncSetAttribute(gemm_mma<3,0>, cudaFuncAttributeMaxDynamicSharedMemorySize, GEMM_SMEM);
    cudaFuncSetAttribute(gemm_mma<1,0>, cudaFuncAttributeMaxDynamicSharedMemorySize, GEMM_SMEM);
    cudaFuncSetAttribute(gemm_mma<3,1>, cudaFuncAttributeMaxDynamicSharedMemorySize, GEMM_SMEM);
    cudaFuncSetAttribute(gemm_mma<1,2>, cudaFuncAttributeMaxDynamicSharedMemorySize, GEMM_SMEM);
    cudaFuncSetAttribute(gemm_mma<3,3>, cudaFuncAttributeMaxDynamicSharedMemorySize, GEMM_SMEM);

    const float scale = (float)(1.0 / sqrt(2048.0 * 2047.0 / 2.0));

    // input splits
    copy_split_k<<<dim3(2, 8192, 1), 256>>>(x,       2048, 0, xh,  xl,  0);
    copy_split_k<<<dim3(2, 4096, 1), 256>>>(w_qk,    2048, 0, wqh, wql, 0);
    copy_split_k<<<dim3(2, 2048, 1), 256>>>(w_dense, 2048, 0, wdh, wdl, 0);

    // K1a: k0 (1 product), epilogue -> kth (transposed hi)
    gemm_mma<1,2><<<dim3(16, 64, 1), 256, GEMM_SMEM>>>(
        xh, nullptr, 0, wqh, nullptr, 0, nullptr, 0, 0, 1.f, nullptr,
        kth, nullptr, nullptr);

    // K1b: v (3 products), epilogue -> vh (direct hi) + vth/vtl (transposed split)
    gemm_mma<3,3><<<dim3(16, 64, 1), 256, GEMM_SMEM>>>(
        xh, xl, 0, wqh + 2048ull * 2048ull, wql + 2048ull * 2048ull, 0,
        nullptr, 0, 0, 1.f, nullptr, vth, vtl, vh);

    // K2: s = scale * kth @ vh^T (per batch, 1 product)
    gemm_mma<1,0><<<dim3(16, 16, 4), 256, GEMM_SMEM>>>(
        kth, nullptr, SSQ, vh, nullptr, SSQ, s, 2048, SSQ, scale, nullptr,
        nullptr, nullptr, nullptr);

    // K3: softmax rows -> bf16 splits
    softmax_split_k<<<8192, 256>>>(s, ah, al);

    // K4: q = a @ vt^T; gathered split epilogue
    gemm_mma<3,1><<<dim3(16, 16, 4), 256, GEMM_SMEM>>>(
        ah, al, SSQ, vth, vtl, SSQ, nullptr, 0, 0, 1.f, nullptr,
        qgh, qgl, nullptr);

    // K5: out = qg @ w_dense^T + bias
    gemm_mma<3,0><<<dim3(16, 64, 1), 256, GEMM_SMEM>>>(
        qgh, qgl, 0, wdh, wdl, 0, out, 2048, 0, 1.f, b_dense,
        nullptr, nullptr, nullptr);
}

// round 13
// speedup vs baseline: 2.0755x; 2.0755x over previous
#include <cuda_runtime.h>
#include <cuda_fp16.h>
#include <math.h>
#include <stdint.h>

// Problem: B=4, T=2048, D=2048, HEADS=16
// All-fp16 single-product chain (fp16 eps=2^-11 -> ~7e-4 end-to-end, <1e-3):
//   K1: kv = x @ w_qk^T (fp32 out)          one merged launch, M=8192 N=4096
//   prep: kth=k0^T, vh=v, vth=v^T (fp16)
//   K2: s = scale * kth @ vh^T (fp32)
//   K3: row softmax -> ah (fp16)
//   K4: q = ah @ vth^T, epilogue scatters head-permuted fp16 rows -> qgh
//   K5: out = qgh @ wdh^T + bias
// Engine: mma.sync m16n8k16 f16 (f32 accum), GBK=64, XOR-swizzled 128B rows,
// 3-stage cp.async ring, one __syncthreads per chunk, 2 CTAs/SM.

// ---------------------------------------------------------------- scratch ---
static __device__ float g_kv[33554432];   // 4*2048*4096 fp32
static __device__ float g_s [16777216];   // 4*2048*2048 fp32

static __device__ __half g_xh [16777216];   // x fp16
static __device__ __half g_wqh[8388608];    // w_qk fp16
static __device__ __half g_wdh[4194304];    // w_dense fp16
static __device__ __half g_kth[16777216];   // k0^T
static __device__ __half g_vh [16777216];   // v
static __device__ __half g_vth[16777216];   // v^T
static __device__ __half g_ah [16777216];   // softmax(a)
static __device__ __half g_qgh[16777216];   // gathered q

// --------------------------------------------------------------- helpers ---
__device__ __forceinline__ uint32_t smem_u32(const void* p) {
    uint32_t a;
    asm("{ .reg .u64 t; cvta.to.shared.u64 t, %1; cvt.u32.u64 %0, t; }"
        : "=r"(a) : "l"(p));
    return a;
}
__device__ __forceinline__ void cp16(uint32_t dst, const void* src) {
    asm volatile("cp.async.cg.shared.global [%0], [%1], 16;"
                 :: "r"(dst), "l"(src) : "memory");
}
#define CP_COMMIT() asm volatile("cp.async.commit_group;" ::: "memory")

__device__ __forceinline__ void ldsm4(uint32_t* r, uint32_t addr) {
    asm volatile("ldmatrix.sync.aligned.m8n8.x4.shared.b16 {%0,%1,%2,%3}, [%4];"
                 : "=r"(r[0]), "=r"(r[1]), "=r"(r[2]), "=r"(r[3]) : "r"(addr));
}
__device__ __forceinline__ void mma16816(float* c, const uint32_t* a, const uint32_t* b) {
    asm volatile(
        "mma.sync.aligned.m16n8k16.row.col.f32.f16.f16.f32 "
        "{%0,%1,%2,%3}, {%4,%5,%6,%7}, {%8,%9}, {%0,%1,%2,%3};"
        : "+f"(c[0]), "+f"(c[1]), "+f"(c[2]), "+f"(c[3])
        : "r"(a[0]), "r"(a[1]), "r"(a[2]), "r"(a[3]), "r"(b[0]), "r"(b[1]));
}

// ----------------------------------------------------------- fp16 GEMM -----
// C(m,n) = alpha * sum_k A(m,k)*B(n,k) [+bias(n)]  (single fp16 product)
// EPI 0: fp32 C (+bias).  EPI 1: scatter fp16 rows r=(m&127)*64+z*16+(m>>7).
// K-major fp16 operands, row length 2048, K=2048. Block 128x128, GBK=64,
// 8 warps (2x4), warp tile 64x32, XOR swizzle on 128B rows, 3-ring, 2 CTA/SM.
#define GK       2048
#define GBK      64
#define NCHUNK   (GK / GBK)        // 32
#define ROWB     128u              // 64 halves per row
#define TILE_B   (128u * ROWB)     // 16384
#define STAGE_B  (2u * TILE_B)     // 32768 (A + B)
#define GEMM_SMEM (3u * STAGE_B)   // 98304 -> 2 CTAs/SM
#define SSQ      4194304ull        // 2048*2048

template<int EPI>
__global__ __launch_bounds__(256, 2)
void gemm_f16(const __half* __restrict__ A, size_t strideA,
              const __half* __restrict__ B, size_t strideB,
              float* __restrict__ C, int ldc, size_t strideC,
              float alpha, const float* __restrict__ bias,
              __half* __restrict__ gh)
{
    extern __shared__ char smem[];
    const uint32_t sbase = smem_u32(smem);

    const int tid  = threadIdx.x;
    const int lane = tid & 31;
    const int wid  = tid >> 5;
    const int wm0  = (wid & 1) * 64;
    const int wn0  = (wid >> 1) * 32;

    A += blockIdx.z * strideA;
    B += blockIdx.z * strideB;
    if (EPI == 0) C += blockIdx.z * strideC;
    const int m0 = blockIdx.y * 128;
    const int n0 = blockIdx.x * 128;

    // loader: 8 x 16B chunks per 128B row; lr = row 0..31, 4 row-blocks
    const int lc = tid & 7;
    const int lr = tid >> 3;

    auto load_stage = [&](int t) {
        if (t < NCHUNK) {
            const uint32_t sb = sbase + (uint32_t)(t % 3) * STAGE_B;
            const int ks = t * GBK;
#pragma unroll
            for (int i = 0; i < 4; i++) {
                const uint32_t row = (uint32_t)(lr + i * 32);
                const uint32_t d = row * ROWB + (((uint32_t)lc ^ (row & 7u)) << 4);
                cp16(sb + d,          A + (size_t)(m0 + row) * GK + ks + lc * 8);
                cp16(sb + TILE_B + d, B + (size_t)(n0 + row) * GK + ks + lc * 8);
            }
        }
        CP_COMMIT();
    };

    float acc[4][4][4];
#pragma unroll
    for (int i = 0; i < 4; i++)
#pragma unroll
        for (int j = 0; j < 4; j++)
#pragma unroll
            for (int k = 0; k < 4; k++) acc[i][j][k] = 0.f;

    const uint32_t a_row  = (uint32_t)(wm0 + (lane & 15));
    const uint32_t a_hi   = (uint32_t)(lane >> 4);         // k 0-7 / 8-15 half
    const uint32_t a_sx   = a_row & 7u;
    const uint32_t a_base = a_row * ROWB;

    const uint32_t b_row  = (uint32_t)(wn0 + ((lane >> 4) & 1) * 8 + (lane & 7));
    const uint32_t b_hi   = (uint32_t)((lane >> 3) & 1);
    const uint32_t b_sx   = b_row & 7u;
    const uint32_t b_base = b_row * ROWB;

    load_stage(0);
    load_stage(1);

    for (int t = 0; t < NCHUNK; t++) {
        asm volatile("cp.async.wait_group 1;" ::: "memory");   // stage t landed
        __syncthreads();                                       // slot (t-1)%3 free
        load_stage(t + 2);

        const uint32_t sb = sbase + (uint32_t)(t % 3) * STAGE_B;
#pragma unroll
        for (int kk = 0; kk < 4; kk++) {
            const uint32_t ax = (((2u * kk + a_hi) ^ a_sx) << 4);
            const uint32_t bx = (((2u * kk + b_hi) ^ b_sx) << 4);
            uint32_t af[4][4], bf[2][4];
#pragma unroll
            for (int mt = 0; mt < 4; mt++)
                ldsm4(af[mt], sb + a_base + (uint32_t)mt * (16u * ROWB) + ax);
#pragma unroll
            for (int p = 0; p < 2; p++)
                ldsm4(bf[p], sb + TILE_B + b_base + (uint32_t)p * (16u * ROWB) + bx);
#pragma unroll
            for (int mt = 0; mt < 4; mt++)
#pragma unroll
                for (int p = 0; p < 2; p++) {
                    mma16816(acc[mt][2 * p + 0], af[mt], &bf[p][0]);
                    mma16816(acc[mt][2 * p + 1], af[mt], &bf[p][2]);
                }
        }
    }

    // ---- epilogue ----
    const int er = lane >> 2;
    const int ec = (lane & 3) * 2;
#pragma unroll
    for (int mt = 0; mt < 4; mt++)
#pragma unroll
        for (int nt = 0; nt < 4; nt++) {
            int m = m0 + wm0 + mt * 16 + er;
            int n = n0 + wn0 + nt * 8 + ec;
            if (EPI == 0) {
                float b0 = 0.f, b1 = 0.f;
                if (bias) { b0 = __ldg(bias + n); b1 = __ldg(bias + n + 1); }
                float2 v0, v1;
                v0.x = alpha * acc[mt][nt][0] + b0;
                v0.y = alpha * acc[mt][nt][1] + b1;
                v1.x = alpha * acc[mt][nt][2] + b0;
                v1.y = alpha * acc[mt][nt][3] + b1;
                *(float2*)&C[(size_t)m * (size_t)ldc + n]       = v0;
                *(float2*)&C[(size_t)(m + 8) * (size_t)ldc + n] = v1;
            } else {
                const int b = (int)blockIdx.z;
                int r1 = ((m & 127) << 6) + b * 16 + (m >> 7);
                int m2 = m + 8;
                int r2 = ((m2 & 127) << 6) + b * 16 + (m2 >> 7);
                *(__half2*)(gh + (size_t)r1 * 2048 + n) =
                    __halves2half2(__float2half(acc[mt][nt][0]),
                                   __float2half(acc[mt][nt][1]));
                *(__half2*)(gh + (size_t)r2 * 2048 + n) =
                    __halves2half2(__float2half(acc[mt][nt][2]),
                                   __float2half(acc[mt][nt][3]));
            }
        }
}

// ----------------------------------------------------------- prep kernels ---
// fp32 [rows x 2048] -> fp16 copy
__global__ __launch_bounds__(256)
void copy_conv(const float* __restrict__ src, size_t src_rstride, size_t src_bstride,
               __half* __restrict__ dst, size_t dst_bstride)
{
    size_t row = blockIdx.y;
    size_t col = (size_t)blockIdx.x * 1024 + threadIdx.x * 4;
    float4 v = *(const float4*)(src + (size_t)blockIdx.z * src_bstride + row * src_rstride + col);
    size_t o = (size_t)blockIdx.z * dst_bstride + row * 2048 + col;
    ((__half2*)(dst + o))[0] = __halves2half2(__float2half(v.x), __float2half(v.y));
    ((__half2*)(dst + o))[1] = __halves2half2(__float2half(v.z), __float2half(v.w));
}

// dst[i][m] = fp16(src[m][i]); per batch 2048x2048
__global__ __launch_bounds__(256)
void transpose_conv(const float* __restrict__ src, size_t src_bstride, int src_ld,
                    __half* __restrict__ dst, size_t dst_bstride)
{
    __shared__ float tile[32][33];
    int tx = threadIdx.x, ty = threadIdx.y;      // blockDim (32, 8)
    int i0 = blockIdx.x * 32, m0 = blockIdx.y * 32;
    const float* s = src + (size_t)blockIdx.z * src_bstride;
#pragma unroll
    for (int r = 0; r < 4; r++)
        tile[ty + r * 8][tx] = s[(size_t)(m0 + ty + r * 8) * src_ld + i0 + tx];
    __syncthreads();
#pragma unroll
    for (int r = 0; r < 4; r++) {
        size_t o = (size_t)blockIdx.z * dst_bstride +
                   (size_t)(i0 + ty + r * 8) * 2048 + m0 + tx;
        dst[o] = __float2half(tile[tx][ty + r * 8]);
    }
}

// Row softmax over 2048 cols; emits fp16 probabilities.
__global__ __launch_bounds__(256)
void softmax_conv(const float* __restrict__ s, __half* __restrict__ a)
{
    const float* p = s + (size_t)blockIdx.x * 2048;
    int tid = threadIdx.x, warp = tid >> 5, lane = tid & 31;
    __shared__ float red[8];

    float4 v0 = *(const float4*)(p + tid * 4);
    float4 v1 = *(const float4*)(p + 1024 + tid * 4);

    float m = fmaxf(fmaxf(fmaxf(v0.x, v0.y), fmaxf(v0.z, v0.w)),
                    fmaxf(fmaxf(v1.x, v1.y), fmaxf(v1.z, v1.w)));
#pragma unroll
    for (int o = 16; o > 0; o >>= 1) m = fmaxf(m, __shfl_xor_sync(0xffffffffu, m, o));
    if (lane == 0) red[warp] = m;
    __syncthreads();
    float bm = red[0];
#pragma unroll
    for (int i = 1; i < 8; i++) bm = fmaxf(bm, red[i]);
    __syncthreads();

    v0.x = __expf(v0.x - bm); v0.y = __expf(v0.y - bm);
    v0.z = __expf(v0.z - bm); v0.w = __expf(v0.w - bm);
    v1.x = __expf(v1.x - bm); v1.y = __expf(v1.y - bm);
    v1.z = __expf(v1.z - bm); v1.w = __expf(v1.w - bm);

    float sm = v0.x + v0.y + v0.z + v0.w + v1.x + v1.y + v1.z + v1.w;
#pragma unroll
    for (int o = 16; o > 0; o >>= 1) sm += __shfl_xor_sync(0xffffffffu, sm, o);
    if (lane == 0) red[warp] = sm;
    __syncthreads();
    float tot = red[0];
#pragma unroll
    for (int i = 1; i < 8; i++) tot += red[i];
    float inv = 1.f / tot;

    size_t base = (size_t)blockIdx.x * 2048;
    ((__half2*)(a + base + tid * 4))[0] =
        __halves2half2(__float2half(v0.x * inv), __float2half(v0.y * inv));
    ((__half2*)(a + base + tid * 4))[1] =
        __halves2half2(__float2half(v0.z * inv), __float2half(v0.w * inv));
    ((__half2*)(a + base + 1024 + tid * 4))[0] =
        __halves2half2(__float2half(v1.x * inv), __float2half(v1.y * inv));
    ((__half2*)(a + base + 1024 + tid * 4))[1] =
        __halves2half2(__float2half(v1.z * inv), __float2half(v1.w * inv));
}

// ------------------------------------------------------------------ driver ---
extern "C" void kernel_launch(void* const* d_in, const int* in_sizes, int n_in,
                              void* d_out, int out_size)
{
    const float* x       = (const float*)d_in[0];
    const float* w_qk    = (const float*)d_in[1];
    const float* w_dense = (const float*)d_in[2];
    const float* b_dense = (const float*)d_in[3];
    float* out = (float*)d_out;

    float *kv, *s;
    cudaGetSymbolAddress((void**)&kv, g_kv);
    cudaGetSymbolAddress((void**)&s,  g_s);
    __half *xh, *wqh, *wdh, *kth, *vh, *vth, *ah, *qgh;
    cudaGetSymbolAddress((void**)&xh,  g_xh);
    cudaGetSymbolAddress((void**)&wqh, g_wqh);
    cudaGetSymbolAddress((void**)&wdh, g_wdh);
    cudaGetSymbolAddress((void**)&kth, g_kth);
    cudaGetSymbolAddress((void**)&vh,  g_vh);
    cudaGetSymbolAddress((void**)&vth, g_vth);
    cudaGetSymbolAddress((void**)&ah,  g_ah);
    cudaGetSymbolAddress((void**)&qgh, g_qgh);

    cudaFuncSetAttribute(gemm_f16<0>, cudaFuncAttributeMaxDynamicSharedMemorySize, GEMM_SMEM);
    cudaFuncSetAttribute(gemm_f16<1>, cudaFuncAttributeMaxDynamicSharedMemorySize, GEMM_SMEM);

    const float scale = (float)(1.0 / sqrt(2048.0 * 2047.0 / 2.0));
    const size_t sKV = 2048ull * 4096ull;

    // fp16 conversions of inputs
    copy_conv<<<dim3(2, 8192, 1), 256>>>(x,       2048, 0, xh,  0);
    copy_conv<<<dim3(2, 4096, 1), 256>>>(w_qk,    2048, 0, wqh, 0);
    copy_conv<<<dim3(2, 2048, 1), 256>>>(w_dense, 2048, 0, wdh, 0);

    // K1: kv = x @ w_qk^T   M=8192 N=4096 (merged k0|v)
    gemm_f16<0><<<dim3(32, 64, 1), 256, GEMM_SMEM>>>(
        xh, 0, wqh, 0, kv, 4096, 0, 1.f, nullptr, nullptr);

    // preps: kt = k0^T, vh = v, vt = v^T (all fp16)
    transpose_conv<<<dim3(64, 64, 4), dim3(32, 8)>>>(kv,        sKV, 4096, kth, SSQ);
    copy_conv     <<<dim3(2, 2048, 4), 256>>>      (kv + 2048, 4096, sKV, vh,  SSQ);
    transpose_conv<<<dim3(64, 64, 4), dim3(32, 8)>>>(kv + 2048, sKV, 4096, vth, SSQ);

    // K2: s = scale * kth @ vh^T (per batch)
    gemm_f16<0><<<dim3(16, 16, 4), 256, GEMM_SMEM>>>(
        kth, SSQ, vh, SSQ, s, 2048, SSQ, scale, nullptr, nullptr);

    // K3: softmax -> fp16 a
    softmax_conv<<<8192, 256>>>(s, ah);

    // K4: q = a @ vt^T; scatter head-permuted fp16 rows
    gemm_f16<1><<<dim3(16, 16, 4), 256, GEMM_SMEM>>>(
        ah, SSQ, vth, SSQ, nullptr, 0, 0, 1.f, nullptr, qgh);

    // K5: out = qg @ w_dense^T + bias
    gemm_f16<0><<<dim3(16, 64, 1), 256, GEMM_SMEM>>>(
        qgh, 0, wdh, 0, out, 2048, 0, 1.f, b_dense, nullptr);
}

// round 14
// speedup vs baseline: 2.1587x; 1.0401x over previous
#include <cuda_runtime.h>
#include <cuda_fp16.h>
#include <math.h>
#include <stdint.h>

// Problem: B=4, T=2048, D=2048, HEADS=16
// All-fp16 single-product chain (~5e-4 end-to-end):
//   K1: kvh = fp16(x @ w_qk^T)              merged, fp16 epilogue, ldc=4096
//   prep: kth = k0^T, vth = v^T (fp16->fp16 transposes; v itself used in-place)
//   K2: sh = fp16(scale * kth @ v^T)        B = kvh+2048 (ldb=4096)
//   K3: row softmax (fp16 in) -> ah fp16
//   K4: q = ah @ vth^T, scatter head-permuted fp16 rows -> qgh
//   K5: out = qgh @ wdh^T + bias (fp32)
// Engine: mma.sync m16n8k16 f16/f32, GBK=64, XOR-swizzled 128B rows,
// 3-stage cp.async ring, one __syncthreads per chunk, 2 CTAs/SM.

// ---------------------------------------------------------------- scratch ---
static __device__ __half g_kvh[33554432];   // 4*2048*4096 (k0 | v)
static __device__ __half g_sh [16777216];   // logits fp16
static __device__ __half g_xh [16777216];
static __device__ __half g_wqh[8388608];
static __device__ __half g_wdh[4194304];
static __device__ __half g_kth[16777216];   // k0^T
static __device__ __half g_vth[16777216];   // v^T
static __device__ __half g_ah [16777216];
static __device__ __half g_qgh[16777216];

// --------------------------------------------------------------- helpers ---
__device__ __forceinline__ uint32_t smem_u32(const void* p) {
    uint32_t a;
    asm("{ .reg .u64 t; cvta.to.shared.u64 t, %1; cvt.u32.u64 %0, t; }"
        : "=r"(a) : "l"(p));
    return a;
}
__device__ __forceinline__ void cp16(uint32_t dst, const void* src) {
    asm volatile("cp.async.cg.shared.global [%0], [%1], 16;"
                 :: "r"(dst), "l"(src) : "memory");
}
#define CP_COMMIT() asm volatile("cp.async.commit_group;" ::: "memory")

__device__ __forceinline__ void ldsm4(uint32_t* r, uint32_t addr) {
    asm volatile("ldmatrix.sync.aligned.m8n8.x4.shared.b16 {%0,%1,%2,%3}, [%4];"
                 : "=r"(r[0]), "=r"(r[1]), "=r"(r[2]), "=r"(r[3]) : "r"(addr));
}
__device__ __forceinline__ void mma16816(float* c, const uint32_t* a, const uint32_t* b) {
    asm volatile(
        "mma.sync.aligned.m16n8k16.row.col.f32.f16.f16.f32 "
        "{%0,%1,%2,%3}, {%4,%5,%6,%7}, {%8,%9}, {%0,%1,%2,%3};"
        : "+f"(c[0]), "+f"(c[1]), "+f"(c[2]), "+f"(c[3])
        : "r"(a[0]), "r"(a[1]), "r"(a[2]), "r"(a[3]), "r"(b[0]), "r"(b[1]));
}

// ----------------------------------------------------------- fp16 GEMM -----
// C(m,n) = alpha * sum_k A(m,k)*B(n,k) [+bias(n)]  (single fp16 product)
// EPI 0: fp32 C (+bias).
// EPI 1: scatter fp16 rows r=(m&127)*64 + z*16 + (m>>7) into gh (ld 2048).
// EPI 2: fp16 C (alpha applied).
// K-major fp16 operands (row strides lda/ldb), K=2048. Block 128x128, GBK=64,
// 8 warps (2x4), warp tile 64x32, XOR swizzle on 128B rows, 3-ring, 2 CTA/SM.
#define GK       2048
#define GBK      64
#define NCHUNK   (GK / GBK)        // 32
#define ROWB     128u              // 64 halves per row
#define TILE_B   (128u * ROWB)     // 16384
#define STAGE_B  (2u * TILE_B)     // 32768
#define GEMM_SMEM (3u * STAGE_B)   // 98304 -> 2 CTAs/SM
#define SSQ      4194304ull        // 2048*2048

template<int EPI>
__global__ __launch_bounds__(256, 2)
void gemm_f16(const __half* __restrict__ A, int lda, size_t strideA,
              const __half* __restrict__ B, int ldb, size_t strideB,
              float* __restrict__ C, __half* __restrict__ Ch,
              int ldc, size_t strideC,
              float alpha, const float* __restrict__ bias,
              __half* __restrict__ gh)
{
    extern __shared__ char smem[];
    const uint32_t sbase = smem_u32(smem);

    const int tid  = threadIdx.x;
    const int lane = tid & 31;
    const int wid  = tid >> 5;
    const int wm0  = (wid & 1) * 64;
    const int wn0  = (wid >> 1) * 32;

    A += blockIdx.z * strideA;
    B += blockIdx.z * strideB;
    if (EPI == 0) C  += blockIdx.z * strideC;
    if (EPI == 2) Ch += blockIdx.z * strideC;
    const int m0 = blockIdx.y * 128;
    const int n0 = blockIdx.x * 128;

    const int lc = tid & 7;    // 16B chunk in 128B row
    const int lr = tid >> 3;   // row 0..31 (x4 blocks)

    auto load_stage = [&](int t) {
        if (t < NCHUNK) {
            const uint32_t sb = sbase + (uint32_t)(t % 3) * STAGE_B;
            const int ks = t * GBK;
#pragma unroll
            for (int i = 0; i < 4; i++) {
                const uint32_t row = (uint32_t)(lr + i * 32);
                const uint32_t d = row * ROWB + (((uint32_t)lc ^ (row & 7u)) << 4);
                cp16(sb + d,          A + (size_t)(m0 + row) * lda + ks + lc * 8);
                cp16(sb + TILE_B + d, B + (size_t)(n0 + row) * ldb + ks + lc * 8);
            }
        }
        CP_COMMIT();
    };

    float acc[4][4][4];
#pragma unroll
    for (int i = 0; i < 4; i++)
#pragma unroll
        for (int j = 0; j < 4; j++)
#pragma unroll
            for (int k = 0; k < 4; k++) acc[i][j][k] = 0.f;

    const uint32_t a_row  = (uint32_t)(wm0 + (lane & 15));
    const uint32_t a_hi   = (uint32_t)(lane >> 4);
    const uint32_t a_sx   = a_row & 7u;
    const uint32_t a_base = a_row * ROWB;

    const uint32_t b_row  = (uint32_t)(wn0 + ((lane >> 4) & 1) * 8 + (lane & 7));
    const uint32_t b_hi   = (uint32_t)((lane >> 3) & 1);
    const uint32_t b_sx   = b_row & 7u;
    const uint32_t b_base = b_row * ROWB;

    load_stage(0);
    load_stage(1);

    for (int t = 0; t < NCHUNK; t++) {
        asm volatile("cp.async.wait_group 1;" ::: "memory");   // stage t landed
        __syncthreads();                                       // slot (t-1)%3 free
        load_stage(t + 2);

        const uint32_t sb = sbase + (uint32_t)(t % 3) * STAGE_B;
#pragma unroll
        for (int kk = 0; kk < 4; kk++) {
            const uint32_t ax = (((2u * kk + a_hi) ^ a_sx) << 4);
            const uint32_t bx = (((2u * kk + b_hi) ^ b_sx) << 4);
            uint32_t af[4][4], bf[2][4];
#pragma unroll
            for (int mt = 0; mt < 4; mt++)
                ldsm4(af[mt], sb + a_base + (uint32_t)mt * (16u * ROWB) + ax);
#pragma unroll
            for (int p = 0; p < 2; p++)
                ldsm4(bf[p], sb + TILE_B + b_base + (uint32_t)p * (16u * ROWB) + bx);
#pragma unroll
            for (int mt = 0; mt < 4; mt++)
#pragma unroll
                for (int p = 0; p < 2; p++) {
                    mma16816(acc[mt][2 * p + 0], af[mt], &bf[p][0]);
                    mma16816(acc[mt][2 * p + 1], af[mt], &bf[p][2]);
                }
        }
    }

    // ---- epilogue ----
    const int er = lane >> 2;
    const int ec = (lane & 3) * 2;
#pragma unroll
    for (int mt = 0; mt < 4; mt++)
#pragma unroll
        for (int nt = 0; nt < 4; nt++) {
            int m = m0 + wm0 + mt * 16 + er;
            int n = n0 + wn0 + nt * 8 + ec;
            if (EPI == 0) {
                float b0 = 0.f, b1 = 0.f;
                if (bias) { b0 = __ldg(bias + n); b1 = __ldg(bias + n + 1); }
                float2 v0, v1;
                v0.x = alpha * acc[mt][nt][0] + b0;
                v0.y = alpha * acc[mt][nt][1] + b1;
                v1.x = alpha * acc[mt][nt][2] + b0;
                v1.y = alpha * acc[mt][nt][3] + b1;
                *(float2*)&C[(size_t)m * (size_t)ldc + n]       = v0;
                *(float2*)&C[(size_t)(m + 8) * (size_t)ldc + n] = v1;
            } else if (EPI == 1) {
                const int b = (int)blockIdx.z;
                int r1 = ((m & 127) << 6) + b * 16 + (m >> 7);
                int m2 = m + 8;
                int r2 = ((m2 & 127) << 6) + b * 16 + (m2 >> 7);
                *(__half2*)(gh + (size_t)r1 * 2048 + n) =
                    __halves2half2(__float2half(acc[mt][nt][0]),
                                   __float2half(acc[mt][nt][1]));
                *(__half2*)(gh + (size_t)r2 * 2048 + n) =
                    __halves2half2(__float2half(acc[mt][nt][2]),
                                   __float2half(acc[mt][nt][3]));
            } else {
                *(__half2*)(Ch + (size_t)m * (size_t)ldc + n) =
                    __halves2half2(__float2half(alpha * acc[mt][nt][0]),
                                   __float2half(alpha * acc[mt][nt][1]));
                *(__half2*)(Ch + (size_t)(m + 8) * (size_t)ldc + n) =
                    __halves2half2(__float2half(alpha * acc[mt][nt][2]),
                                   __float2half(alpha * acc[mt][nt][3]));
            }
        }
}

// ----------------------------------------------------------- prep kernels ---
// fp32 [rows x 2048] -> fp16
__global__ __launch_bounds__(256)
void copy_conv(const float* __restrict__ src, __half* __restrict__ dst)
{
    size_t row = blockIdx.y;
    size_t col = (size_t)blockIdx.x * 1024 + threadIdx.x * 4;
    float4 v = *(const float4*)(src + row * 2048 + col);
    size_t o = row * 2048 + col;
    ((__half2*)(dst + o))[0] = __halves2half2(__float2half(v.x), __float2half(v.y));
    ((__half2*)(dst + o))[1] = __halves2half2(__float2half(v.z), __float2half(v.w));
}

// fp16 transpose: dst[i][m] = src[m][i], 2048x2048 per batch, 64x64 tiles
__global__ __launch_bounds__(256)
void transpose_h(const __half* __restrict__ src, int src_ld, size_t src_bstride,
                 __half* __restrict__ dst, size_t dst_bstride)
{
    __shared__ __half tile[64][65];
    const int tid = threadIdx.x;
    const int cp  = tid & 31;      // col pair 0..31
    const int r0  = tid >> 5;      // 0..7
    const int m0 = blockIdx.y * 64, i0 = blockIdx.x * 64;
    const __half* s = src + blockIdx.z * src_bstride;
#pragma unroll
    for (int i = 0; i < 8; i++) {
        int row = r0 + i * 8;
        __half2 v = *(const __half2*)(s + (size_t)(m0 + row) * src_ld + i0 + 2 * cp);
        tile[row][2 * cp]     = __low2half(v);
        tile[row][2 * cp + 1] = __high2half(v);
    }
    __syncthreads();
    __half* d = dst + blockIdx.z * dst_bstride;
#pragma unroll
    for (int i = 0; i < 8; i++) {
        int irow = r0 + i * 8;
        __half2 v = __halves2half2(tile[2 * cp][irow], tile[2 * cp + 1][irow]);
        *(__half2*)(d + (size_t)(i0 + irow) * 2048 + m0 + 2 * cp) = v;
    }
}

// Row softmax, fp16 in -> fp16 out, 2048 cols, 256 threads x 8 elems.
__global__ __launch_bounds__(256)
void softmax_h(const __half* __restrict__ s, __half* __restrict__ a)
{
    const __half* p = s + (size_t)blockIdx.x * 2048;
    int tid = threadIdx.x, warp = tid >> 5, lane = tid & 31;
    __shared__ float red[8];

    __half hv[8];
    *(uint4*)hv = *(const uint4*)(p + tid * 8);
    float f[8];
#pragma unroll
    for (int i = 0; i < 8; i++) f[i] = __half2float(hv[i]);

    float m = f[0];
#pragma unroll
    for (int i = 1; i < 8; i++) m = fmaxf(m, f[i]);
#pragma unroll
    for (int o = 16; o > 0; o >>= 1) m = fmaxf(m, __shfl_xor_sync(0xffffffffu, m, o));
    if (lane == 0) red[warp] = m;
    __syncthreads();
    float bm = red[0];
#pragma unroll
    for (int i = 1; i < 8; i++) bm = fmaxf(bm, red[i]);
    __syncthreads();

    float sm = 0.f;
#pragma unroll
    for (int i = 0; i < 8; i++) { f[i] = __expf(f[i] - bm); sm += f[i]; }
#pragma unroll
    for (int o = 16; o > 0; o >>= 1) sm += __shfl_xor_sync(0xffffffffu, sm, o);
    if (lane == 0) red[warp] = sm;
    __syncthreads();
    float tot = red[0];
#pragma unroll
    for (int i = 1; i < 8; i++) tot += red[i];
    float inv = 1.f / tot;

    __half2 o2[4];
#pragma unroll
    for (int i = 0; i < 4; i++)
        o2[i] = __halves2half2(__float2half(f[2 * i] * inv),
                               __float2half(f[2 * i + 1] * inv));
    *(uint4*)(a + (size_t)blockIdx.x * 2048 + tid * 8) = *(uint4*)o2;
}

// ------------------------------------------------------------------ driver ---
extern "C" void kernel_launch(void* const* d_in, const int* in_sizes, int n_in,
                              void* d_out, int out_size)
{
    const float* x       = (const float*)d_in[0];
    const float* w_qk    = (const float*)d_in[1];
    const float* w_dense = (const float*)d_in[2];
    const float* b_dense = (const float*)d_in[3];
    float* out = (float*)d_out;

    __half *kvh, *sh, *xh, *wqh, *wdh, *kth, *vth, *ah, *qgh;
    cudaGetSymbolAddress((void**)&kvh, g_kvh);
    cudaGetSymbolAddress((void**)&sh,  g_sh);
    cudaGetSymbolAddress((void**)&xh,  g_xh);
    cudaGetSymbolAddress((void**)&wqh, g_wqh);
    cudaGetSymbolAddress((void**)&wdh, g_wdh);
    cudaGetSymbolAddress((void**)&kth, g_kth);
    cudaGetSymbolAddress((void**)&vth, g_vth);
    cudaGetSymbolAddress((void**)&ah,  g_ah);
    cudaGetSymbolAddress((void**)&qgh, g_qgh);

    cudaFuncSetAttribute(gemm_f16<0>, cudaFuncAttributeMaxDynamicSharedMemorySize, GEMM_SMEM);
    cudaFuncSetAttribute(gemm_f16<1>, cudaFuncAttributeMaxDynamicSharedMemorySize, GEMM_SMEM);
    cudaFuncSetAttribute(gemm_f16<2>, cudaFuncAttributeMaxDynamicSharedMemorySize, GEMM_SMEM);

    const float scale = (float)(1.0 / sqrt(2048.0 * 2047.0 / 2.0));
    const size_t sKV = 2048ull * 4096ull;

    // fp16 conversions of inputs
    copy_conv<<<dim3(2, 8192, 1), 256>>>(x,       xh);
    copy_conv<<<dim3(2, 4096, 1), 256>>>(w_qk,    wqh);
    copy_conv<<<dim3(2, 2048, 1), 256>>>(w_dense, wdh);

    // K1: kvh = fp16(x @ w_qk^T)   M=8192 N=4096, fp16 epilogue
    gemm_f16<2><<<dim3(32, 64, 1), 256, GEMM_SMEM>>>(
        xh, 2048, 0, wqh, 2048, 0, nullptr, kvh, 4096, 0, 1.f, nullptr, nullptr);

    // preps: kth = k0^T, vth = v^T (fp16 transposes; v used in-place for K2)
    transpose_h<<<dim3(32, 32, 4), 256>>>(kvh,        4096, sKV, kth, SSQ);
    transpose_h<<<dim3(32, 32, 4), 256>>>(kvh + 2048, 4096, sKV, vth, SSQ);

    // K2: sh = fp16(scale * kth @ v^T)   B = v half of kvh, ldb=4096
    gemm_f16<2><<<dim3(16, 16, 4), 256, GEMM_SMEM>>>(
        kth, 2048, SSQ, kvh + 2048, 4096, sKV, nullptr, sh, 2048, SSQ,
        scale, nullptr, nullptr);

    // K3: softmax -> fp16 a
    softmax_h<<<8192, 256>>>(sh, ah);

    // K4: q = a @ vt^T; scatter head-permuted fp16 rows
    gemm_f16<1><<<dim3(16, 16, 4), 256, GEMM_SMEM>>>(
        ah, 2048, SSQ, vth, 2048, SSQ, nullptr, nullptr, 0, 0, 1.f, nullptr, qgh);

    // K5: out = qg @ w_dense^T + bias
    gemm_f16<0><<<dim3(16, 64, 1), 256, GEMM_SMEM>>>(
        qgh, 2048, 0, wdh, 2048, 0, out, nullptr, 2048, 0, 1.f, b_dense, nullptr);
}